// round 6
// baseline (speedup 1.0000x reference)
#include <cuda_runtime.h>
#include <cstdint>

#define N_MAX  100000
#define E_MAXC 3200000
#define IN_F   512
#define HID    16
#define NCLS   7

typedef unsigned long long ull;

// ---- scratch (no allocations allowed) ----
__device__ int    s_cnt[N_MAX];       // in-degree (excl. self-loop)
__device__ int    s_row[N_MAX];       // CSR row start
__device__ int    s_cur[N_MAX];       // fill cursor
__device__ int    s_bsum[512];        // per-block totals from scanA
__device__ float  s_dinv[N_MAX];
__device__ float4 s_g1[N_MAX * 4];    // [N][16]: dinv * (x@W1)
__device__ float4 s_g2[N_MAX * 2];    // [N][8] (col 7 pad): dinv * (h@W2)
__device__ int    s_csr[E_MAXC];      // src indices grouped by dst

// ---- f32x2 packed math (sm_100+) ----
#define FMA2(d, a, b, c) asm("fma.rn.f32x2 %0, %1, %2, %3;" : "=l"(d) : "l"(a), "l"(b), "l"(c))
#define ADD2(d, a, b)    asm("add.rn.f32x2 %0, %1, %2;"     : "=l"(d) : "l"(a), "l"(b))
#define MUL2(d, a, b)    asm("mul.rn.f32x2 %0, %1, %2;"     : "=l"(d) : "l"(a), "l"(b))
#define PACK2(d, s)      asm("mov.b64 %0, {%1, %1};"        : "=l"(d) : "r"(__float_as_uint(s)))
#define PACKAB(d, lo, hi) asm("mov.b64 %0, {%1, %2};"       : "=l"(d) : "f"(lo), "f"(hi))

__device__ __forceinline__ float lo32(ull p) { return __uint_as_float((unsigned)p); }
__device__ __forceinline__ float hi32(ull p) { return __uint_as_float((unsigned)(p >> 32)); }

// ================= build =================
__global__ void k_zero(int n) {
    int i = blockIdx.x * blockDim.x + threadIdx.x;
    if (i < n) s_cnt[i] = 0;
}

__global__ void k_hist(const int* __restrict__ dst, int e) {
    int i = blockIdx.x * blockDim.x + threadIdx.x;
    if (i < e) atomicAdd(&s_cnt[dst[i]], 1);
}

__global__ void k_scanA(int n) {              // per-block scan, totals to s_bsum
    __shared__ int sh[256];
    const int t = threadIdx.x;
    const int i = blockIdx.x * 256 + t;
    int v = (i < n) ? s_cnt[i] : 0;
    sh[t] = v;
    __syncthreads();
    #pragma unroll
    for (int off = 1; off < 256; off <<= 1) {
        int add = (t >= off) ? sh[t - off] : 0;
        __syncthreads();
        sh[t] += add;
        __syncthreads();
    }
    if (i < n) s_row[i] = sh[t] - v;          // exclusive within block
    if (t == 255) s_bsum[blockIdx.x] = sh[255];
}

// scanB folded in: each block reduces s_bsum[0..blockIdx) itself (<=391 ints)
__global__ void k_scanC(int n) {
    __shared__ int red[256];
    const int t = threadIdx.x;
    const int b = blockIdx.x;
    int p = 0;
    for (int j = t; j < b; j += 256) p += s_bsum[j];
    red[t] = p;
    __syncthreads();
    #pragma unroll
    for (int off = 128; off >= 1; off >>= 1) {
        if (t < off) red[t] += red[t + off];
        __syncthreads();
    }
    const int base = red[0];
    const int i = b * 256 + t;
    if (i >= n) return;
    int st = s_row[i] + base;
    s_row[i] = st;
    s_cur[i] = st;
    s_dinv[i] = rsqrtf((float)(s_cnt[i] + 1));   // +1 self-loop
}

__global__ void k_fill(const int* __restrict__ src, const int* __restrict__ dst, int e) {
    int i = blockIdx.x * blockDim.x + threadIdx.x;
    if (i >= e) return;
    int p = atomicAdd(&s_cur[dst[i]], 1);
    s_csr[p] = src[i];
}

// ================= layer-1 GEMM: g1[i] = dinv[i] * (x[i] @ W1) =================
// Thread-per-row, 8 f32x2 accumulators. W (32KB) in smem, warp-uniform LDS.128
// broadcasts. X streamed in 256-row x 16-k tiles, cp.async double-buffered.
// float4-slot swizzle q' = q ^ ((row>>1)&3): conflict-free for both staged
// stores and the per-thread 4x LDS.128 reads. smem = 64KB -> 3 blocks/SM.
#define G1_ROWS 256
#define KT      16

#define STAGE_G1(buf, tt)                                                          \
    {                                                                              \
        _Pragma("unroll")                                                          \
        for (int i_ = 0; i_ < 4; i_++) {                                           \
            int lin  = i_ * 256 + t;                                               \
            int row  = lin >> 2, q = lin & 3;                                      \
            int qp   = q ^ ((row >> 1) & 3);                                       \
            int grow = rowbase + row;                                              \
            unsigned dp = (unsigned)__cvta_generic_to_shared(                      \
                &Xs[(buf)][row * 4 + qp]);                                         \
            const float* gp = x + (size_t)grow * IN_F + (tt) * KT + q * 4;         \
            if (grow < n)                                                          \
                asm volatile("cp.async.ca.shared.global [%0], [%1], 16;"           \
                             :: "r"(dp), "l"(gp));                                 \
        }                                                                          \
    }

__global__ void __launch_bounds__(256, 3) k_gemm1(const float* __restrict__ x,
                                                  const float* __restrict__ W1, int n) {
    __shared__ float  Ws[IN_F * HID];     // 32 KB
    __shared__ float4 Xs[2][G1_ROWS * 4]; // 2 x 16 KB

    const int t = threadIdx.x;
    const int rowbase = blockIdx.x * G1_ROWS;

    STAGE_G1(0, 0);
    asm volatile("cp.async.commit_group;");

    #pragma unroll
    for (int i = 0; i < 8; i++)
        ((float4*)Ws)[i * 256 + t] = ((const float4*)W1)[i * 256 + t];

    ull acc[8] = {0, 0, 0, 0, 0, 0, 0, 0};
    const int sw = (t >> 1) & 3;

    __syncthreads();   // Ws visible

    for (int tile = 0; tile < IN_F / KT; tile++) {
        if (tile + 1 < IN_F / KT) STAGE_G1((tile + 1) & 1, tile + 1);
        asm volatile("cp.async.commit_group;");
        asm volatile("cp.async.wait_group 1;");
        __syncthreads();   // cross-thread visibility of buf `tile`

        const float4* xb = &Xs[tile & 1][t * 4];
        float4 xv[4];
        #pragma unroll
        for (int q = 0; q < 4; q++) xv[q] = xb[q ^ sw];

        #pragma unroll
        for (int q = 0; q < 4; q++) {
            #pragma unroll
            for (int j = 0; j < 4; j++) {
                ull xx;
                PACK2(xx, ((const float*)&xv[q])[j]);
                const ulonglong2* wr =
                    (const ulonglong2*)(Ws + (tile * KT + q * 4 + j) * HID);
                ulonglong2 wa = wr[0], wb = wr[1], wc = wr[2], wd = wr[3];
                FMA2(acc[0], xx, wa.x, acc[0]); FMA2(acc[1], xx, wa.y, acc[1]);
                FMA2(acc[2], xx, wb.x, acc[2]); FMA2(acc[3], xx, wb.y, acc[3]);
                FMA2(acc[4], xx, wc.x, acc[4]); FMA2(acc[5], xx, wc.y, acc[5]);
                FMA2(acc[6], xx, wd.x, acc[6]); FMA2(acc[7], xx, wd.y, acc[7]);
            }
        }
        __syncthreads();   // WAR: next stage overwrites this buf
    }

    const int myrow = rowbase + t;
    if (myrow >= n) return;

    const float di = s_dinv[myrow];
    ull dd;
    PACK2(dd, di);
    #pragma unroll
    for (int jj = 0; jj < 8; jj++) MUL2(acc[jj], acc[jj], dd);

    #pragma unroll
    for (int m = 0; m < 4; m++) {
        float4 v;
        v.x = lo32(acc[2 * m]);     v.y = hi32(acc[2 * m]);
        v.z = lo32(acc[2 * m + 1]); v.w = hi32(acc[2 * m + 1]);
        s_g1[(size_t)myrow * 4 + m] = v;
    }
}

// ================= layer-1 gather + fused mid =================
// 4 lanes per dst node; lane m owns cols [4m,4m+4). CSR index loads shared via
// width-4 shfl with the GROUP mask (the 4 lanes share g/cnt so they are
// converged; full-warp mask here is UB because trip counts diverge per group).
__global__ void __launch_bounds__(256) k_gather1(const float* __restrict__ b1,
                                                 const float* __restrict__ W2, int n) {
    __shared__ float W2s[HID * NCLS];
    __shared__ float b1s[HID];
    const int t = threadIdx.x;
    if (t < HID * NCLS) W2s[t] = W2[t];
    if (t < HID)        b1s[t] = b1[t];
    __syncthreads();

    const int g = (blockIdx.x * 256 + t) >> 2;
    const int m = t & 3;
    if (g >= n) return;

    const unsigned gm = 0xFu << (t & 28);     // mask of my 4-lane group

    const ulonglong2* G1 = (const ulonglong2*)s_g1;
    ulonglong2 acc = G1[(size_t)g * 4 + m];
    const int cnt = s_cnt[g];
    const int* cp = s_csr + s_row[g];

    int it = 0;
    for (; it + 3 < cnt; it += 4) {
        int my = __ldg(cp + it + m);                       // coalesced 16B / group
        int i0 = __shfl_sync(gm, my, 0, 4);
        int i1 = __shfl_sync(gm, my, 1, 4);
        int i2 = __shfl_sync(gm, my, 2, 4);
        int i3 = __shfl_sync(gm, my, 3, 4);
        ulonglong2 v0 = __ldg(&G1[(size_t)i0 * 4 + m]);
        ulonglong2 v1 = __ldg(&G1[(size_t)i1 * 4 + m]);
        ulonglong2 v2 = __ldg(&G1[(size_t)i2 * 4 + m]);
        ulonglong2 v3 = __ldg(&G1[(size_t)i3 * 4 + m]);
        ADD2(acc.x, acc.x, v0.x); ADD2(acc.y, acc.y, v0.y);
        ADD2(acc.x, acc.x, v1.x); ADD2(acc.y, acc.y, v1.y);
        ADD2(acc.x, acc.x, v2.x); ADD2(acc.y, acc.y, v2.y);
        ADD2(acc.x, acc.x, v3.x); ADD2(acc.y, acc.y, v3.y);
    }
    for (; it < cnt; it++) {
        int i0 = __ldg(cp + it);
        ulonglong2 v0 = __ldg(&G1[(size_t)i0 * 4 + m]);
        ADD2(acc.x, acc.x, v0.x); ADD2(acc.y, acc.y, v0.y);
    }

    const float di = s_dinv[g];
    float h[4];
    h[0] = fmaxf(fmaf(di, lo32(acc.x), b1s[m * 4 + 0]), 0.f);
    h[1] = fmaxf(fmaf(di, hi32(acc.x), b1s[m * 4 + 1]), 0.f);
    h[2] = fmaxf(fmaf(di, lo32(acc.y), b1s[m * 4 + 2]), 0.f);
    h[3] = fmaxf(fmaf(di, hi32(acc.y), b1s[m * 4 + 3]), 0.f);

    float u[8] = {0.f, 0.f, 0.f, 0.f, 0.f, 0.f, 0.f, 0.f};
    #pragma unroll
    for (int jj = 0; jj < 4; jj++) {
        const int j = m * 4 + jj;
        #pragma unroll
        for (int c = 0; c < NCLS; c++)
            u[c] = fmaf(h[jj], W2s[j * NCLS + c], u[c]);
    }

    ull p[4];
    PACKAB(p[0], u[0], u[1]);
    PACKAB(p[1], u[2], u[3]);
    PACKAB(p[2], u[4], u[5]);
    PACKAB(p[3], u[6], u[7]);
    #pragma unroll
    for (int off = 1; off <= 2; off <<= 1) {
        #pragma unroll
        for (int q = 0; q < 4; q++) {
            ull o = __shfl_xor_sync(gm, p[q], off, 4);
            ADD2(p[q], p[q], o);
        }
    }
    ull dd;
    PACK2(dd, di);
    #pragma unroll
    for (int q = 0; q < 4; q++) MUL2(p[q], p[q], dd);

    if (m == 0) {
        float4 v = make_float4(lo32(p[0]), hi32(p[0]), lo32(p[1]), hi32(p[1]));
        s_g2[(size_t)g * 2 + 0] = v;
    } else if (m == 1) {
        float4 v = make_float4(lo32(p[2]), hi32(p[2]), lo32(p[3]), hi32(p[3]));
        s_g2[(size_t)g * 2 + 1] = v;
    }
}

// ================= layer-2 gather + fused final output =================
__global__ void __launch_bounds__(256) k_gather2(const float* __restrict__ b2,
                                                 float* __restrict__ out, int n) {
    const int t = threadIdx.x;
    const int g = (blockIdx.x * 256 + t) >> 2;
    const int m = t & 3;
    if (g >= n) return;

    const unsigned gm = 0xFu << (t & 28);

    const ull* G2 = (const ull*)s_g2;
    ull acc = G2[(size_t)g * 4 + m];
    const int cnt = s_cnt[g];
    const int* cp = s_csr + s_row[g];

    int it = 0;
    for (; it + 3 < cnt; it += 4) {
        int my = __ldg(cp + it + m);
        int i0 = __shfl_sync(gm, my, 0, 4);
        int i1 = __shfl_sync(gm, my, 1, 4);
        int i2 = __shfl_sync(gm, my, 2, 4);
        int i3 = __shfl_sync(gm, my, 3, 4);
        ull v0 = __ldg(&G2[(size_t)i0 * 4 + m]);
        ull v1 = __ldg(&G2[(size_t)i1 * 4 + m]);
        ull v2 = __ldg(&G2[(size_t)i2 * 4 + m]);
        ull v3 = __ldg(&G2[(size_t)i3 * 4 + m]);
        ADD2(acc, acc, v0); ADD2(acc, acc, v1);
        ADD2(acc, acc, v2); ADD2(acc, acc, v3);
    }
    for (; it < cnt; it++) {
        int i0 = __ldg(cp + it);
        ull v0 = __ldg(&G2[(size_t)i0 * 4 + m]);
        ADD2(acc, acc, v0);
    }

    const float di = s_dinv[g];
    const int c0 = m * 2;
    float* orow = out + (size_t)g * NCLS;
    orow[c0] = fmaf(di, lo32(acc), __ldg(b2 + c0));
    if (c0 + 1 < NCLS)
        orow[c0 + 1] = fmaf(di, hi32(acc), __ldg(b2 + c0 + 1));
}

extern "C" void kernel_launch(void* const* d_in, const int* in_sizes, int n_in,
                              void* d_out, int out_size) {
    const float* x  = (const float*)d_in[0];
    const int*   ei = (const int*)  d_in[1];
    const float* W1 = (const float*)d_in[2];
    const float* b1 = (const float*)d_in[3];
    const float* W2 = (const float*)d_in[4];
    const float* b2 = (const float*)d_in[5];
    float* out = (float*)d_out;

    const int n = in_sizes[0] / IN_F;     // 100000
    const int e = in_sizes[1] / 2;        // 3200000
    const int* src = ei;
    const int* dst = ei + e;

    const int nb = (n + 255) / 256;
    const int eb = (e + 255) / 256;
    const int gb = (n + G1_ROWS - 1) / G1_ROWS;
    const int g4 = (4 * n + 255) / 256;

    k_zero   <<<nb, 256>>>(n);
    k_hist   <<<eb, 256>>>(dst, e);
    k_scanA  <<<nb, 256>>>(n);
    k_scanC  <<<nb, 256>>>(n);
    k_fill   <<<eb, 256>>>(src, dst, e);
    k_gemm1  <<<gb, 256>>>(x, W1, n);
    k_gather1<<<g4, 256>>>(b1, W2, n);
    k_gather2<<<g4, 256>>>(b2, out, n);
}

// round 7
// speedup vs baseline: 1.0997x; 1.0997x over previous
#include <cuda_runtime.h>
#include <cstdint>

#define N_MAX  100000
#define E_MAXC 3200000
#define IN_F   512
#define HID    16
#define NCLS   7

typedef unsigned long long ull;

// ---- scratch (no allocations allowed) ----
__device__ int    s_cnt[N_MAX];       // in-degree (excl. self-loop)
__device__ int    s_row[N_MAX];       // CSR row start
__device__ int    s_cur[N_MAX];       // fill cursor
__device__ int    s_bsum[512];        // per-block totals from scanA
__device__ float  s_dinv[N_MAX];
__device__ float4 s_g1[N_MAX * 4];    // [N][16]: dinv * (x@W1)
__device__ float4 s_g2[N_MAX * 2];    // [N][8] (col 7 pad): dinv * (h@W2)
__device__ int    s_csr[E_MAXC];      // src indices grouped by dst

// ---- f32x2 packed math (sm_100+) ----
#define FMA2(d, a, b, c) asm("fma.rn.f32x2 %0, %1, %2, %3;" : "=l"(d) : "l"(a), "l"(b), "l"(c))
#define ADD2(d, a, b)    asm("add.rn.f32x2 %0, %1, %2;"     : "=l"(d) : "l"(a), "l"(b))
#define MUL2(d, a, b)    asm("mul.rn.f32x2 %0, %1, %2;"     : "=l"(d) : "l"(a), "l"(b))
#define PACK2(d, s)      asm("mov.b64 %0, {%1, %1};"        : "=l"(d) : "r"(__float_as_uint(s)))
#define PACKAB(d, lo, hi) asm("mov.b64 %0, {%1, %2};"       : "=l"(d) : "f"(lo), "f"(hi))

__device__ __forceinline__ float lo32(ull p) { return __uint_as_float((unsigned)p); }
__device__ __forceinline__ float hi32(ull p) { return __uint_as_float((unsigned)(p >> 32)); }

// ================= build =================
__global__ void k_zero(int n) {
    int i = blockIdx.x * blockDim.x + threadIdx.x;
    if (i < n) s_cnt[i] = 0;
}

__global__ void k_hist(const int* __restrict__ dst, int e) {
    int i = blockIdx.x * blockDim.x + threadIdx.x;
    const int e4 = e >> 2;
    if (i < e4) {
        int4 d = ((const int4*)dst)[i];
        atomicAdd(&s_cnt[d.x], 1);
        atomicAdd(&s_cnt[d.y], 1);
        atomicAdd(&s_cnt[d.z], 1);
        atomicAdd(&s_cnt[d.w], 1);
    }
    int r = e4 * 4 + i;                   // tail (e % 4 edges)
    if (i < (e & 3)) atomicAdd(&s_cnt[dst[r]], 1);
}

__global__ void k_scanA(int n) {              // per-block scan, totals to s_bsum
    __shared__ int sh[256];
    const int t = threadIdx.x;
    const int i = blockIdx.x * 256 + t;
    int v = (i < n) ? s_cnt[i] : 0;
    sh[t] = v;
    __syncthreads();
    #pragma unroll
    for (int off = 1; off < 256; off <<= 1) {
        int add = (t >= off) ? sh[t - off] : 0;
        __syncthreads();
        sh[t] += add;
        __syncthreads();
    }
    if (i < n) s_row[i] = sh[t] - v;          // exclusive within block
    if (t == 255) s_bsum[blockIdx.x] = sh[255];
}

// scanB folded in: each block reduces s_bsum[0..blockIdx) itself (<=391 ints)
__global__ void k_scanC(int n) {
    __shared__ int red[256];
    const int t = threadIdx.x;
    const int b = blockIdx.x;
    int p = 0;
    for (int j = t; j < b; j += 256) p += s_bsum[j];
    red[t] = p;
    __syncthreads();
    #pragma unroll
    for (int off = 128; off >= 1; off >>= 1) {
        if (t < off) red[t] += red[t + off];
        __syncthreads();
    }
    const int base = red[0];
    const int i = b * 256 + t;
    if (i >= n) return;
    int st = s_row[i] + base;
    s_row[i] = st;
    s_cur[i] = st;
    s_dinv[i] = rsqrtf((float)(s_cnt[i] + 1));   // +1 self-loop
}

__global__ void k_fill(const int* __restrict__ src, const int* __restrict__ dst, int e) {
    int i = blockIdx.x * blockDim.x + threadIdx.x;
    const int e4 = e >> 2;
    if (i < e4) {
        int4 s = ((const int4*)src)[i];
        int4 d = ((const int4*)dst)[i];
        s_csr[atomicAdd(&s_cur[d.x], 1)] = s.x;
        s_csr[atomicAdd(&s_cur[d.y], 1)] = s.y;
        s_csr[atomicAdd(&s_cur[d.z], 1)] = s.z;
        s_csr[atomicAdd(&s_cur[d.w], 1)] = s.w;
    }
    int r = e4 * 4 + i;
    if (i < (e & 3)) s_csr[atomicAdd(&s_cur[dst[r]], 1)] = src[r];
}

// ================= layer-1 GEMM: g1[i] = dinv[i] * (x[i] @ W1) =================
// Barrier-free warp-private pipeline. 128 threads = 4 warps; each warp owns 32
// rows (row = warpbase + lane) and double-buffers its own 32row x 32k (4KB)
// X tile via cp.async, synced only by wait_group + __syncwarp. W (32KB) is
// block-shared smem read as warp-uniform LDS.128 broadcasts (one __syncthreads
// total, after the W load). Swizzle: float4 slot q' = q ^ (row&7) -- staging
// STS.128 phases are 8 same-row lanes hitting 8 distinct slots (32 banks),
// compute LDS.128 phases are 8 rows x distinct slots -> conflict-free.
#define KT 32

#define STAGE_W(buf, tt)                                                           \
    {                                                                              \
        _Pragma("unroll")                                                          \
        for (int i_ = 0; i_ < 8; i_++) {                                           \
            int lin = i_ * 32 + lane;                                              \
            int wr_ = lin >> 3, q = lin & 7;     /* row-in-warp, float4 slot */    \
            int qp  = q ^ (wr_ & 7);                                               \
            unsigned dp = (unsigned)__cvta_generic_to_shared(                      \
                &Xw[(buf)][wr_ * 8 + qp]);                                         \
            const float* gp = x + (size_t)(warprow + wr_) * IN_F + (tt) * KT + q * 4; \
            if (warprow + wr_ < n)                                                 \
                asm volatile("cp.async.ca.shared.global [%0], [%1], 16;"           \
                             :: "r"(dp), "l"(gp));                                 \
        }                                                                          \
    }

__global__ void __launch_bounds__(128, 3) k_gemm1(const float* __restrict__ x,
                                                  const float* __restrict__ W1, int n) {
    __shared__ float  Ws[IN_F * HID];        // 32 KB
    __shared__ float4 Xs[4][2][256];         // 4 warps x 2 bufs x 4KB = 32 KB

    const int t    = threadIdx.x;
    const int w    = t >> 5;
    const int lane = t & 31;
    const int warprow = blockIdx.x * 128 + w * 32;
    float4 (*Xw)[256] = Xs[w];

    STAGE_W(0, 0);
    asm volatile("cp.async.commit_group;");

    // load W (block-cooperative), single block barrier
    #pragma unroll
    for (int i = 0; i < 16; i++)
        ((float4*)Ws)[i * 128 + t] = ((const float4*)W1)[i * 128 + t];
    __syncthreads();

    ull acc[8] = {0, 0, 0, 0, 0, 0, 0, 0};
    const int sw = lane & 7;

    #pragma unroll 1
    for (int tile = 0; tile < IN_F / KT; tile++) {
        if (tile + 1 < IN_F / KT) STAGE_W((tile + 1) & 1, tile + 1);
        asm volatile("cp.async.commit_group;");
        asm volatile("cp.async.wait_group 1;");
        __syncwarp();                         // buf[tile&1] visible warp-wide

        const float4* xb = &Xw[tile & 1][lane * 8];
        #pragma unroll
        for (int q = 0; q < 8; q++) {
            float4 xv = xb[q ^ sw];
            #pragma unroll
            for (int j = 0; j < 4; j++) {
                ull xx;
                PACK2(xx, ((const float*)&xv)[j]);
                const ulonglong2* wr =
                    (const ulonglong2*)(Ws + (tile * KT + q * 4 + j) * HID);
                ulonglong2 wa = wr[0], wb = wr[1], wc = wr[2], wd = wr[3];
                FMA2(acc[0], xx, wa.x, acc[0]); FMA2(acc[1], xx, wa.y, acc[1]);
                FMA2(acc[2], xx, wb.x, acc[2]); FMA2(acc[3], xx, wb.y, acc[3]);
                FMA2(acc[4], xx, wc.x, acc[4]); FMA2(acc[5], xx, wc.y, acc[5]);
                FMA2(acc[6], xx, wd.x, acc[6]); FMA2(acc[7], xx, wd.y, acc[7]);
            }
        }
        __syncwarp();                         // WAR: next stage rewrites this buf
    }

    const int myrow = warprow + lane;
    if (myrow >= n) return;

    const float di = s_dinv[myrow];
    ull dd;
    PACK2(dd, di);
    #pragma unroll
    for (int jj = 0; jj < 8; jj++) MUL2(acc[jj], acc[jj], dd);

    #pragma unroll
    for (int m = 0; m < 4; m++) {
        float4 v;
        v.x = lo32(acc[2 * m]);     v.y = hi32(acc[2 * m]);
        v.z = lo32(acc[2 * m + 1]); v.w = hi32(acc[2 * m + 1]);
        s_g1[(size_t)myrow * 4 + m] = v;
    }
}

// ================= layer-1 gather + fused mid (R4 proven-fast form) =================
// 4 lanes per dst node; lane m owns cols [4m,4m+4). Redundant-but-parallel
// index loads (L1 hits, full MLP) -- measured faster than shfl sharing.
__global__ void __launch_bounds__(256) k_gather1(const float* __restrict__ b1,
                                                 const float* __restrict__ W2, int n) {
    __shared__ float W2s[HID * NCLS];
    __shared__ float b1s[HID];
    const int t = threadIdx.x;
    if (t < HID * NCLS) W2s[t] = W2[t];
    if (t < HID)        b1s[t] = b1[t];
    __syncthreads();

    const int g = (blockIdx.x * 256 + t) >> 2;
    const int m = t & 3;
    if (g >= n) return;

    const ulonglong2* G1 = (const ulonglong2*)s_g1;
    ulonglong2 acc = G1[(size_t)g * 4 + m];
    const int cnt = s_cnt[g];
    const int* cp = s_csr + s_row[g];

    int it = 0;
    for (; it + 3 < cnt; it += 4) {
        int i0 = __ldg(cp + it), i1 = __ldg(cp + it + 1);
        int i2 = __ldg(cp + it + 2), i3 = __ldg(cp + it + 3);
        ulonglong2 v0 = __ldg(&G1[(size_t)i0 * 4 + m]);
        ulonglong2 v1 = __ldg(&G1[(size_t)i1 * 4 + m]);
        ulonglong2 v2 = __ldg(&G1[(size_t)i2 * 4 + m]);
        ulonglong2 v3 = __ldg(&G1[(size_t)i3 * 4 + m]);
        ADD2(acc.x, acc.x, v0.x); ADD2(acc.y, acc.y, v0.y);
        ADD2(acc.x, acc.x, v1.x); ADD2(acc.y, acc.y, v1.y);
        ADD2(acc.x, acc.x, v2.x); ADD2(acc.y, acc.y, v2.y);
        ADD2(acc.x, acc.x, v3.x); ADD2(acc.y, acc.y, v3.y);
    }
    for (; it < cnt; it++) {
        int i0 = __ldg(cp + it);
        ulonglong2 v0 = __ldg(&G1[(size_t)i0 * 4 + m]);
        ADD2(acc.x, acc.x, v0.x); ADD2(acc.y, acc.y, v0.y);
    }

    const float di = s_dinv[g];
    float h[4];
    h[0] = fmaxf(fmaf(di, lo32(acc.x), b1s[m * 4 + 0]), 0.f);
    h[1] = fmaxf(fmaf(di, hi32(acc.x), b1s[m * 4 + 1]), 0.f);
    h[2] = fmaxf(fmaf(di, lo32(acc.y), b1s[m * 4 + 2]), 0.f);
    h[3] = fmaxf(fmaf(di, hi32(acc.y), b1s[m * 4 + 3]), 0.f);

    float u[8] = {0.f, 0.f, 0.f, 0.f, 0.f, 0.f, 0.f, 0.f};
    #pragma unroll
    for (int jj = 0; jj < 4; jj++) {
        const int j = m * 4 + jj;
        #pragma unroll
        for (int c = 0; c < NCLS; c++)
            u[c] = fmaf(h[jj], W2s[j * NCLS + c], u[c]);
    }

    ull p[4];
    PACKAB(p[0], u[0], u[1]);
    PACKAB(p[1], u[2], u[3]);
    PACKAB(p[2], u[4], u[5]);
    PACKAB(p[3], u[6], u[7]);
    #pragma unroll
    for (int off = 1; off <= 2; off <<= 1) {
        #pragma unroll
        for (int q = 0; q < 4; q++) {
            ull o = __shfl_xor_sync(0xffffffffu, p[q], off);
            ADD2(p[q], p[q], o);
        }
    }
    ull dd;
    PACK2(dd, di);
    #pragma unroll
    for (int q = 0; q < 4; q++) MUL2(p[q], p[q], dd);

    if (m == 0) {
        float4 v = make_float4(lo32(p[0]), hi32(p[0]), lo32(p[1]), hi32(p[1]));
        s_g2[(size_t)g * 2 + 0] = v;
    } else if (m == 1) {
        float4 v = make_float4(lo32(p[2]), hi32(p[2]), lo32(p[3]), hi32(p[3]));
        s_g2[(size_t)g * 2 + 1] = v;
    }
}

// ================= layer-2 gather + fused final output =================
__global__ void __launch_bounds__(256) k_gather2(const float* __restrict__ b2,
                                                 float* __restrict__ out, int n) {
    const int t = threadIdx.x;
    const int g = (blockIdx.x * 256 + t) >> 2;
    const int m = t & 3;
    if (g >= n) return;

    const ull* G2 = (const ull*)s_g2;
    ull acc = G2[(size_t)g * 4 + m];
    const int cnt = s_cnt[g];
    const int* cp = s_csr + s_row[g];

    int it = 0;
    for (; it + 3 < cnt; it += 4) {
        int i0 = __ldg(cp + it), i1 = __ldg(cp + it + 1);
        int i2 = __ldg(cp + it + 2), i3 = __ldg(cp + it + 3);
        ull v0 = __ldg(&G2[(size_t)i0 * 4 + m]);
        ull v1 = __ldg(&G2[(size_t)i1 * 4 + m]);
        ull v2 = __ldg(&G2[(size_t)i2 * 4 + m]);
        ull v3 = __ldg(&G2[(size_t)i3 * 4 + m]);
        ADD2(acc, acc, v0); ADD2(acc, acc, v1);
        ADD2(acc, acc, v2); ADD2(acc, acc, v3);
    }
    for (; it < cnt; it++) {
        int i0 = __ldg(cp + it);
        ull v0 = __ldg(&G2[(size_t)i0 * 4 + m]);
        ADD2(acc, acc, v0);
    }

    const float di = s_dinv[g];
    const int c0 = m * 2;
    float* orow = out + (size_t)g * NCLS;
    orow[c0] = fmaf(di, lo32(acc), __ldg(b2 + c0));
    if (c0 + 1 < NCLS)
        orow[c0 + 1] = fmaf(di, hi32(acc), __ldg(b2 + c0 + 1));
}

extern "C" void kernel_launch(void* const* d_in, const int* in_sizes, int n_in,
                              void* d_out, int out_size) {
    const float* x  = (const float*)d_in[0];
    const int*   ei = (const int*)  d_in[1];
    const float* W1 = (const float*)d_in[2];
    const float* b1 = (const float*)d_in[3];
    const float* W2 = (const float*)d_in[4];
    const float* b2 = (const float*)d_in[5];
    float* out = (float*)d_out;

    const int n = in_sizes[0] / IN_F;     // 100000
    const int e = in_sizes[1] / 2;        // 3200000
    const int* src = ei;
    const int* dst = ei + e;

    const int nb = (n + 255) / 256;
    const int e4b = (e / 4 + 255) / 256;
    const int gb = (n + 127) / 128;
    const int g4 = (4 * n + 255) / 256;

    k_zero   <<<nb, 256>>>(n);
    k_hist   <<<e4b, 256>>>(dst, e);
    k_scanA  <<<nb, 256>>>(n);
    k_scanC  <<<nb, 256>>>(n);
    k_fill   <<<e4b, 256>>>(src, dst, e);
    k_gemm1  <<<gb, 128>>>(x, W1, n);
    k_gather1<<<g4, 256>>>(b1, W2, n);
    k_gather2<<<g4, 256>>>(b2, out, n);
}

// round 8
// speedup vs baseline: 1.2388x; 1.1265x over previous
#include <cuda_runtime.h>
#include <cstdint>

#define N_MAX  100000
#define E_MAXC 3200000
#define E_PAD  (E_MAXC + 8 * N_MAX)   // CSR capacity with per-row pad to mult of 8
#define IN_F   512
#define HID    16
#define NCLS   7

typedef unsigned long long ull;

// ---- scratch (no allocations allowed) ----
__device__ int    s_cnt[N_MAX];            // true in-degree (excl. self-loop)
__device__ int    s_row[N_MAX];            // CSR row start (padded layout)
__device__ int    s_cur[N_MAX];            // fill cursor
__device__ int    s_bsum[512];             // per-block totals from scanA
__device__ float  s_dinv[N_MAX];
__device__ float4 s_g1[(N_MAX + 1) * 4];   // [N+1][16]; row N = zeros (sentinel)
__device__ float4 s_g2[(N_MAX + 1) * 2];   // [N+1][8];  row N = zeros (sentinel)
__device__ int    s_csr[E_PAD];            // src indices grouped by dst, pad = n

// ---- f32x2 packed math (sm_100+) ----
#define FMA2(d, a, b, c) asm("fma.rn.f32x2 %0, %1, %2, %3;" : "=l"(d) : "l"(a), "l"(b), "l"(c))
#define ADD2(d, a, b)    asm("add.rn.f32x2 %0, %1, %2;"     : "=l"(d) : "l"(a), "l"(b))
#define MUL2(d, a, b)    asm("mul.rn.f32x2 %0, %1, %2;"     : "=l"(d) : "l"(a), "l"(b))
#define PACK2(d, s)      asm("mov.b64 %0, {%1, %1};"        : "=l"(d) : "r"(__float_as_uint(s)))
#define PACKAB(d, lo, hi) asm("mov.b64 %0, {%1, %2};"       : "=l"(d) : "f"(lo), "f"(hi))

__device__ __forceinline__ float lo32(ull p) { return __uint_as_float((unsigned)p); }
__device__ __forceinline__ float hi32(ull p) { return __uint_as_float((unsigned)(p >> 32)); }

// ================= build =================
// zero cnt, preset CSR with sentinel n, zero sentinel rows of g1/g2
__global__ void k_zero(int n, int csr4) {
    int i = blockIdx.x * blockDim.x + threadIdx.x;
    if (i < n) s_cnt[i] = 0;
    if (i < csr4) ((int4*)s_csr)[i] = make_int4(n, n, n, n);
    if (i < 4) s_g1[(size_t)n * 4 + i] = make_float4(0.f, 0.f, 0.f, 0.f);
    if (i < 2) s_g2[(size_t)n * 2 + i] = make_float4(0.f, 0.f, 0.f, 0.f);
}

__global__ void k_hist(const int* __restrict__ dst, int e) {
    int i = blockIdx.x * blockDim.x + threadIdx.x;
    if (i < e) atomicAdd(&s_cnt[dst[i]], 1);
}

__global__ void k_scanA(int n) {              // scan of PADDED counts
    __shared__ int sh[256];
    const int t = threadIdx.x;
    const int i = blockIdx.x * 256 + t;
    int v = (i < n) ? ((s_cnt[i] + 7) & ~7) : 0;
    sh[t] = v;
    __syncthreads();
    #pragma unroll
    for (int off = 1; off < 256; off <<= 1) {
        int add = (t >= off) ? sh[t - off] : 0;
        __syncthreads();
        sh[t] += add;
        __syncthreads();
    }
    if (i < n) s_row[i] = sh[t] - v;          // exclusive within block
    if (t == 255) s_bsum[blockIdx.x] = sh[255];
}

// scanB folded in: each block reduces s_bsum[0..blockIdx) itself (<=391 ints)
__global__ void k_scanC(int n) {
    __shared__ int red[256];
    const int t = threadIdx.x;
    const int b = blockIdx.x;
    int p = 0;
    for (int j = t; j < b; j += 256) p += s_bsum[j];
    red[t] = p;
    __syncthreads();
    #pragma unroll
    for (int off = 128; off >= 1; off >>= 1) {
        if (t < off) red[t] += red[t + off];
        __syncthreads();
    }
    const int base = red[0];
    const int i = b * 256 + t;
    if (i >= n) return;
    int st = s_row[i] + base;
    s_row[i] = st;
    s_cur[i] = st;
    s_dinv[i] = rsqrtf((float)(s_cnt[i] + 1));   // +1 self-loop (true degree)
}

__global__ void k_fill(const int* __restrict__ src, const int* __restrict__ dst, int e) {
    int i = blockIdx.x * blockDim.x + threadIdx.x;
    if (i >= e) return;
    int p = atomicAdd(&s_cur[dst[i]], 1);
    s_csr[p] = src[i];
}

// ================= layer-1 GEMM: g1[i] = dinv[i] * (x[i] @ W1) =================
// (R4 proven config) Thread-per-row, 8 f32x2 accumulators. W (32KB) in smem,
// warp-uniform LDS.128 broadcasts. X in 256x8 tiles via cp.async double
// buffering; swizzle q' = q ^ ((row>>1)&1). smem 48KB -> 4 blocks/SM.
#define G1_ROWS 256

#define STAGE(buf, k0)                                                             \
    {                                                                              \
        _Pragma("unroll")                                                          \
        for (int j = 0; j < 2; j++) {                                              \
            int row  = j * 128 + sr;                                               \
            int grow = rowbase + row;                                              \
            int qp   = sq ^ ((row >> 1) & 1);                                      \
            unsigned dstp = (unsigned)__cvta_generic_to_shared(                    \
                &Xs[(buf) * 2048 + row * 8 + qp * 4]);                             \
            const float* gp = x + (size_t)grow * IN_F + (k0) + sq * 4;             \
            if (grow < n)                                                          \
                asm volatile("cp.async.ca.shared.global [%0], [%1], 16;"           \
                             :: "r"(dstp), "l"(gp));                               \
        }                                                                          \
    }

__global__ void __launch_bounds__(256, 4) k_gemm1(const float* __restrict__ x,
                                                  const float* __restrict__ W1, int n) {
    __shared__ float  Ws[IN_F * HID];   // 32 KB
    __shared__ float4 Xs4[2][512];      // 2 x 8 KB  (total static smem = 48 KB)
    float* Xs = (float*)Xs4;

    const int t = threadIdx.x;
    const int rowbase = blockIdx.x * G1_ROWS;
    const int sr = t >> 1, sq = t & 1;  // staging mapping

    STAGE(0, 0);
    asm volatile("cp.async.commit_group;");

    #pragma unroll
    for (int i = 0; i < 8; i++)
        ((float4*)Ws)[i * 256 + t] = ((const float4*)W1)[i * 256 + t];

    ull acc[8] = {0, 0, 0, 0, 0, 0, 0, 0};
    const int ss = (t >> 1) & 1;        // compute-side swizzle for own row (=t)

    for (int tile = 0; tile < 64; tile++) {
        if (tile < 63) STAGE((tile + 1) & 1, (tile + 1) * 8);
        asm volatile("cp.async.commit_group;");
        asm volatile("cp.async.wait_group 1;");
        __syncthreads();

        const float4* xr = (const float4*)&Xs[(tile & 1) * 2048 + t * 8];
        #pragma unroll
        for (int qq = 0; qq < 2; qq++) {
            float4 xv = xr[qq ^ ss];
            #pragma unroll
            for (int jj = 0; jj < 4; jj++) {
                ull xx;
                PACK2(xx, ((const float*)&xv)[jj]);
                const ulonglong2* wr =
                    (const ulonglong2*)(Ws + (tile * 8 + qq * 4 + jj) * HID);
                ulonglong2 wa = wr[0], wb = wr[1], wc = wr[2], wd = wr[3];
                FMA2(acc[0], xx, wa.x, acc[0]); FMA2(acc[1], xx, wa.y, acc[1]);
                FMA2(acc[2], xx, wb.x, acc[2]); FMA2(acc[3], xx, wb.y, acc[3]);
                FMA2(acc[4], xx, wc.x, acc[4]); FMA2(acc[5], xx, wc.y, acc[5]);
                FMA2(acc[6], xx, wd.x, acc[6]); FMA2(acc[7], xx, wd.y, acc[7]);
            }
        }
        __syncthreads();
    }

    const int myrow = rowbase + t;
    if (myrow >= n) return;

    const float di = s_dinv[myrow];
    ull dd;
    PACK2(dd, di);
    #pragma unroll
    for (int jj = 0; jj < 8; jj++) MUL2(acc[jj], acc[jj], dd);

    #pragma unroll
    for (int m = 0; m < 4; m++) {
        float4 v;
        v.x = lo32(acc[2 * m]);     v.y = hi32(acc[2 * m]);
        v.z = lo32(acc[2 * m + 1]); v.w = hi32(acc[2 * m + 1]);
        s_g1[(size_t)myrow * 4 + m] = v;
    }
}

// ================= layer-1 gather + fused mid =================
// 4 lanes per dst node; lane m owns cols [4m,4m+4). Rows padded to mult of 8
// with sentinel (zero row) => single 8-wide unrolled loop, no tail, MLP=8.
__global__ void __launch_bounds__(256) k_gather1(const float* __restrict__ b1,
                                                 const float* __restrict__ W2, int n) {
    __shared__ float W2s[HID * NCLS];
    __shared__ float b1s[HID];
    const int t = threadIdx.x;
    if (t < HID * NCLS) W2s[t] = W2[t];
    if (t < HID)        b1s[t] = b1[t];
    __syncthreads();

    const int g = (blockIdx.x * 256 + t) >> 2;
    const int m = t & 3;
    if (g >= n) return;

    const ulonglong2* G1 = (const ulonglong2*)s_g1;
    ulonglong2 acc = G1[(size_t)g * 4 + m];     // self-loop term
    const int cnt  = s_cnt[g];
    const int pcnt = (cnt + 7) & ~7;
    const int* cp  = s_csr + s_row[g];

    for (int it = 0; it < pcnt; it += 8) {
        int ii[8];
        #pragma unroll
        for (int j = 0; j < 8; j++) ii[j] = __ldg(cp + it + j);
        ulonglong2 v[8];
        #pragma unroll
        for (int j = 0; j < 8; j++) v[j] = __ldg(&G1[(size_t)ii[j] * 4 + m]);
        #pragma unroll
        for (int j = 0; j < 8; j++) {
            ADD2(acc.x, acc.x, v[j].x);
            ADD2(acc.y, acc.y, v[j].y);
        }
    }

    const float di = s_dinv[g];
    float h[4];
    h[0] = fmaxf(fmaf(di, lo32(acc.x), b1s[m * 4 + 0]), 0.f);
    h[1] = fmaxf(fmaf(di, hi32(acc.x), b1s[m * 4 + 1]), 0.f);
    h[2] = fmaxf(fmaf(di, lo32(acc.y), b1s[m * 4 + 2]), 0.f);
    h[3] = fmaxf(fmaf(di, hi32(acc.y), b1s[m * 4 + 3]), 0.f);

    float u[8] = {0.f, 0.f, 0.f, 0.f, 0.f, 0.f, 0.f, 0.f};
    #pragma unroll
    for (int jj = 0; jj < 4; jj++) {
        const int j = m * 4 + jj;
        #pragma unroll
        for (int c = 0; c < NCLS; c++)
            u[c] = fmaf(h[jj], W2s[j * NCLS + c], u[c]);
    }

    ull p[4];
    PACKAB(p[0], u[0], u[1]);
    PACKAB(p[1], u[2], u[3]);
    PACKAB(p[2], u[4], u[5]);
    PACKAB(p[3], u[6], u[7]);
    #pragma unroll
    for (int off = 1; off <= 2; off <<= 1) {
        #pragma unroll
        for (int q = 0; q < 4; q++) {
            ull o = __shfl_xor_sync(0xffffffffu, p[q], off);
            ADD2(p[q], p[q], o);
        }
    }
    ull dd;
    PACK2(dd, di);
    #pragma unroll
    for (int q = 0; q < 4; q++) MUL2(p[q], p[q], dd);

    if (m == 0) {
        float4 v = make_float4(lo32(p[0]), hi32(p[0]), lo32(p[1]), hi32(p[1]));
        s_g2[(size_t)g * 2 + 0] = v;
    } else if (m == 1) {
        float4 v = make_float4(lo32(p[2]), hi32(p[2]), lo32(p[3]), hi32(p[3]));
        s_g2[(size_t)g * 2 + 1] = v;
    }
}

// ================= layer-2 gather + fused final output =================
__global__ void __launch_bounds__(256) k_gather2(const float* __restrict__ b2,
                                                 float* __restrict__ out, int n) {
    const int t = threadIdx.x;
    const int g = (blockIdx.x * 256 + t) >> 2;
    const int m = t & 3;
    if (g >= n) return;

    const ull* G2 = (const ull*)s_g2;
    ull acc = G2[(size_t)g * 4 + m];            // self-loop term
    const int cnt  = s_cnt[g];
    const int pcnt = (cnt + 7) & ~7;
    const int* cp  = s_csr + s_row[g];

    for (int it = 0; it < pcnt; it += 8) {
        int ii[8];
        #pragma unroll
        for (int j = 0; j < 8; j++) ii[j] = __ldg(cp + it + j);
        ull v[8];
        #pragma unroll
        for (int j = 0; j < 8; j++) v[j] = __ldg(&G2[(size_t)ii[j] * 4 + m]);
        #pragma unroll
        for (int j = 0; j < 8; j++) ADD2(acc, acc, v[j]);
    }

    const float di = s_dinv[g];
    const int c0 = m * 2;
    float* orow = out + (size_t)g * NCLS;
    orow[c0] = fmaf(di, lo32(acc), __ldg(b2 + c0));
    if (c0 + 1 < NCLS)
        orow[c0 + 1] = fmaf(di, hi32(acc), __ldg(b2 + c0 + 1));
}

extern "C" void kernel_launch(void* const* d_in, const int* in_sizes, int n_in,
                              void* d_out, int out_size) {
    const float* x  = (const float*)d_in[0];
    const int*   ei = (const int*)  d_in[1];
    const float* W1 = (const float*)d_in[2];
    const float* b1 = (const float*)d_in[3];
    const float* W2 = (const float*)d_in[4];
    const float* b2 = (const float*)d_in[5];
    float* out = (float*)d_out;

    const int n = in_sizes[0] / IN_F;     // 100000
    const int e = in_sizes[1] / 2;        // 3200000
    const int* src = ei;
    const int* dst = ei + e;

    const int csr_len = e + 8 * n;        // padded CSR extent actually used
    const int csr4    = (csr_len + 3) / 4;

    const int nb = (n + 255) / 256;
    const int eb = (e + 255) / 256;
    const int zb = (csr4 > n ? csr4 + 255 : n + 255) / 256;
    const int gb = (n + G1_ROWS - 1) / G1_ROWS;
    const int g4 = (4 * n + 255) / 256;

    k_zero   <<<zb, 256>>>(n, csr4);
    k_hist   <<<eb, 256>>>(dst, e);
    k_scanA  <<<nb, 256>>>(n);
    k_scanC  <<<nb, 256>>>(n);
    k_fill   <<<eb, 256>>>(src, dst, e);
    k_gemm1  <<<gb, 256>>>(x, W1, n);
    k_gather1<<<g4, 256>>>(b1, W2, n);
    k_gather2<<<g4, 256>>>(b2, out, n);
}

// round 9
// speedup vs baseline: 1.2529x; 1.0114x over previous
#include <cuda_runtime.h>
#include <cstdint>

#define N_MAX  100000
#define E_MAXC 3200000
#define E_PAD  (E_MAXC + 8 * N_MAX)   // CSR capacity with per-row pad to mult of 8
#define IN_F   512
#define HID    16
#define NCLS   7

typedef unsigned long long ull;

// ---- scratch (no allocations allowed) ----
__device__ int    s_cnt[N_MAX];            // true in-degree (excl. self-loop)
__device__ int    s_row[N_MAX];            // CSR row start (padded layout)
__device__ int    s_cur[N_MAX];            // fill cursor
__device__ int    s_bsum[512];             // per-block totals from scanA
__device__ float  s_dinv[N_MAX];
__device__ float4 s_g1[(N_MAX + 1) * 4];   // [N+1][16]; row N = zeros (sentinel)
__device__ float4 s_g2[(N_MAX + 1) * 2];   // [N+1][8];  row N = zeros (sentinel)
__device__ int    s_csr[E_PAD];            // src indices grouped by dst, pad = n

// ---- f32x2 packed math (sm_100+) ----
#define FMA2(d, a, b, c) asm("fma.rn.f32x2 %0, %1, %2, %3;" : "=l"(d) : "l"(a), "l"(b), "l"(c))
#define ADD2(d, a, b)    asm("add.rn.f32x2 %0, %1, %2;"     : "=l"(d) : "l"(a), "l"(b))
#define MUL2(d, a, b)    asm("mul.rn.f32x2 %0, %1, %2;"     : "=l"(d) : "l"(a), "l"(b))
#define PACK2(d, s)      asm("mov.b64 %0, {%1, %1};"        : "=l"(d) : "r"(__float_as_uint(s)))
#define PACKAB(d, lo, hi) asm("mov.b64 %0, {%1, %2};"       : "=l"(d) : "f"(lo), "f"(hi))

__device__ __forceinline__ float lo32(ull p) { return __uint_as_float((unsigned)p); }
__device__ __forceinline__ float hi32(ull p) { return __uint_as_float((unsigned)(p >> 32)); }

// ================= build =================
// zero cnt, preset CSR with sentinel n, zero sentinel rows of g1/g2
__global__ void k_zero(int n, int csr4) {
    int i = blockIdx.x * blockDim.x + threadIdx.x;
    if (i < n) s_cnt[i] = 0;
    if (i < csr4) ((int4*)s_csr)[i] = make_int4(n, n, n, n);
    if (i < 4) s_g1[(size_t)n * 4 + i] = make_float4(0.f, 0.f, 0.f, 0.f);
    if (i < 2) s_g2[(size_t)n * 2 + i] = make_float4(0.f, 0.f, 0.f, 0.f);
}

__global__ void k_hist(const int* __restrict__ dst, int e) {
    int i = blockIdx.x * blockDim.x + threadIdx.x;
    if (i < e) atomicAdd(&s_cnt[dst[i]], 1);
}

__global__ void k_scanA(int n) {              // scan of PADDED counts
    __shared__ int sh[256];
    const int t = threadIdx.x;
    const int i = blockIdx.x * 256 + t;
    int v = (i < n) ? ((s_cnt[i] + 7) & ~7) : 0;
    sh[t] = v;
    __syncthreads();
    #pragma unroll
    for (int off = 1; off < 256; off <<= 1) {
        int add = (t >= off) ? sh[t - off] : 0;
        __syncthreads();
        sh[t] += add;
        __syncthreads();
    }
    if (i < n) s_row[i] = sh[t] - v;          // exclusive within block
    if (t == 255) s_bsum[blockIdx.x] = sh[255];
}

// scanB folded in: each block reduces s_bsum[0..blockIdx) itself (<=391 ints)
__global__ void k_scanC(int n) {
    __shared__ int red[256];
    const int t = threadIdx.x;
    const int b = blockIdx.x;
    int p = 0;
    for (int j = t; j < b; j += 256) p += s_bsum[j];
    red[t] = p;
    __syncthreads();
    #pragma unroll
    for (int off = 128; off >= 1; off >>= 1) {
        if (t < off) red[t] += red[t + off];
        __syncthreads();
    }
    const int base = red[0];
    const int i = b * 256 + t;
    if (i >= n) return;
    int st = s_row[i] + base;
    s_row[i] = st;
    s_cur[i] = st;
    s_dinv[i] = rsqrtf((float)(s_cnt[i] + 1));   // +1 self-loop (true degree)
}

__global__ void k_fill(const int* __restrict__ src, const int* __restrict__ dst, int e) {
    int i = blockIdx.x * blockDim.x + threadIdx.x;
    if (i >= e) return;
    int p = atomicAdd(&s_cur[dst[i]], 1);
    s_csr[p] = src[i];
}

// ================= layer-1 GEMM: g1[i] = dinv[i] * (x[i] @ W1) =================
// Thread-per-row, 8 f32x2 accumulators. W (32KB) smem, warp-uniform LDS.128
// broadcasts. X in 256x8 tiles via cp.async with a 4-buffer, 3-tile-deep
// pipeline and ONE __syncthreads per tile:
//   prologue: stage tiles 0..2 (one commit group each)
//   iter t:   wait_group 2 (group t done) -> barrier -> compute buf t&3
//             -> stage tile t+3 into buf (t+3)&3 -> commit
// WAR on buf (t+3)&3 (holds tile t-1) is safe: every thread passed iter-t's
// barrier (after its own iter t-1 compute) before any thread stages there.
#define G1_ROWS 256

#define STAGE(buf, k0)                                                             \
    {                                                                              \
        _Pragma("unroll")                                                          \
        for (int j = 0; j < 2; j++) {                                              \
            int row  = j * 128 + sr;                                               \
            int grow = rowbase + row;                                              \
            int qp   = sq ^ ((row >> 1) & 1);                                      \
            unsigned dstp = (unsigned)__cvta_generic_to_shared(                    \
                &Xs[(buf) * 2048 + row * 8 + qp * 4]);                             \
            const float* gp = x + (size_t)grow * IN_F + (k0) + sq * 4;             \
            if (grow < n)                                                          \
                asm volatile("cp.async.ca.shared.global [%0], [%1], 16;"           \
                             :: "r"(dstp), "l"(gp));                               \
        }                                                                          \
    }

__global__ void __launch_bounds__(256, 3) k_gemm1(const float* __restrict__ x,
                                                  const float* __restrict__ W1, int n) {
    __shared__ float  Ws[IN_F * HID];   // 32 KB
    __shared__ float4 Xs4[4][512];      // 4 x 8 KB  (total static smem = 64 KB)
    float* Xs = (float*)Xs4;

    const int t = threadIdx.x;
    const int rowbase = blockIdx.x * G1_ROWS;
    const int sr = t >> 1, sq = t & 1;  // staging mapping

    STAGE(0, 0);
    asm volatile("cp.async.commit_group;");
    STAGE(1, 8);
    asm volatile("cp.async.commit_group;");
    STAGE(2, 16);
    asm volatile("cp.async.commit_group;");

    #pragma unroll
    for (int i = 0; i < 8; i++)
        ((float4*)Ws)[i * 256 + t] = ((const float4*)W1)[i * 256 + t];

    ull acc[8] = {0, 0, 0, 0, 0, 0, 0, 0};
    const int ss = (t >> 1) & 1;        // compute-side swizzle for own row (=t)

    #pragma unroll 1
    for (int tile = 0; tile < 64; tile++) {
        asm volatile("cp.async.wait_group 2;");   // group `tile` complete
        __syncthreads();                          // visibility + WAR protection

        const float4* xr = (const float4*)&Xs[(tile & 3) * 2048 + t * 8];
        #pragma unroll
        for (int qq = 0; qq < 2; qq++) {
            float4 xv = xr[qq ^ ss];
            #pragma unroll
            for (int jj = 0; jj < 4; jj++) {
                ull xx;
                PACK2(xx, ((const float*)&xv)[jj]);
                const ulonglong2* wr =
                    (const ulonglong2*)(Ws + (tile * 8 + qq * 4 + jj) * HID);
                ulonglong2 wa = wr[0], wb = wr[1], wc = wr[2], wd = wr[3];
                FMA2(acc[0], xx, wa.x, acc[0]); FMA2(acc[1], xx, wa.y, acc[1]);
                FMA2(acc[2], xx, wb.x, acc[2]); FMA2(acc[3], xx, wb.y, acc[3]);
                FMA2(acc[4], xx, wc.x, acc[4]); FMA2(acc[5], xx, wc.y, acc[5]);
                FMA2(acc[6], xx, wd.x, acc[6]); FMA2(acc[7], xx, wd.y, acc[7]);
            }
        }

        if (tile + 3 < 64) {
            STAGE((tile + 3) & 3, (tile + 3) * 8);
            asm volatile("cp.async.commit_group;");
        }
    }

    const int myrow = rowbase + t;
    if (myrow >= n) return;

    const float di = s_dinv[myrow];
    ull dd;
    PACK2(dd, di);
    #pragma unroll
    for (int jj = 0; jj < 8; jj++) MUL2(acc[jj], acc[jj], dd);

    #pragma unroll
    for (int m = 0; m < 4; m++) {
        float4 v;
        v.x = lo32(acc[2 * m]);     v.y = hi32(acc[2 * m]);
        v.z = lo32(acc[2 * m + 1]); v.w = hi32(acc[2 * m + 1]);
        s_g1[(size_t)myrow * 4 + m] = v;
    }
}

// ================= layer-1 gather + fused mid =================
// 4 lanes per dst node; lane m owns cols [4m,4m+4). Rows padded to mult of 8
// with sentinel (zero row) => single 8-wide unrolled loop, no tail, MLP=8.
__global__ void __launch_bounds__(256) k_gather1(const float* __restrict__ b1,
                                                 const float* __restrict__ W2, int n) {
    __shared__ float W2s[HID * NCLS];
    __shared__ float b1s[HID];
    const int t = threadIdx.x;
    if (t < HID * NCLS) W2s[t] = W2[t];
    if (t < HID)        b1s[t] = b1[t];
    __syncthreads();

    const int g = (blockIdx.x * 256 + t) >> 2;
    const int m = t & 3;
    if (g >= n) return;

    const ulonglong2* G1 = (const ulonglong2*)s_g1;
    ulonglong2 acc = G1[(size_t)g * 4 + m];     // self-loop term
    const int cnt  = s_cnt[g];
    const int pcnt = (cnt + 7) & ~7;
    const int* cp  = s_csr + s_row[g];

    for (int it = 0; it < pcnt; it += 8) {
        int ii[8];
        #pragma unroll
        for (int j = 0; j < 8; j++) ii[j] = __ldg(cp + it + j);
        ulonglong2 v[8];
        #pragma unroll
        for (int j = 0; j < 8; j++) v[j] = __ldg(&G1[(size_t)ii[j] * 4 + m]);
        #pragma unroll
        for (int j = 0; j < 8; j++) {
            ADD2(acc.x, acc.x, v[j].x);
            ADD2(acc.y, acc.y, v[j].y);
        }
    }

    const float di = s_dinv[g];
    float h[4];
    h[0] = fmaxf(fmaf(di, lo32(acc.x), b1s[m * 4 + 0]), 0.f);
    h[1] = fmaxf(fmaf(di, hi32(acc.x), b1s[m * 4 + 1]), 0.f);
    h[2] = fmaxf(fmaf(di, lo32(acc.y), b1s[m * 4 + 2]), 0.f);
    h[3] = fmaxf(fmaf(di, hi32(acc.y), b1s[m * 4 + 3]), 0.f);

    float u[8] = {0.f, 0.f, 0.f, 0.f, 0.f, 0.f, 0.f, 0.f};
    #pragma unroll
    for (int jj = 0; jj < 4; jj++) {
        const int j = m * 4 + jj;
        #pragma unroll
        for (int c = 0; c < NCLS; c++)
            u[c] = fmaf(h[jj], W2s[j * NCLS + c], u[c]);
    }

    ull p[4];
    PACKAB(p[0], u[0], u[1]);
    PACKAB(p[1], u[2], u[3]);
    PACKAB(p[2], u[4], u[5]);
    PACKAB(p[3], u[6], u[7]);
    #pragma unroll
    for (int off = 1; off <= 2; off <<= 1) {
        #pragma unroll
        for (int q = 0; q < 4; q++) {
            ull o = __shfl_xor_sync(0xffffffffu, p[q], off);
            ADD2(p[q], p[q], o);
        }
    }
    ull dd;
    PACK2(dd, di);
    #pragma unroll
    for (int q = 0; q < 4; q++) MUL2(p[q], p[q], dd);

    if (m == 0) {
        float4 v = make_float4(lo32(p[0]), hi32(p[0]), lo32(p[1]), hi32(p[1]));
        s_g2[(size_t)g * 2 + 0] = v;
    } else if (m == 1) {
        float4 v = make_float4(lo32(p[2]), hi32(p[2]), lo32(p[3]), hi32(p[3]));
        s_g2[(size_t)g * 2 + 1] = v;
    }
}

// ================= layer-2 gather + fused final output =================
__global__ void __launch_bounds__(256) k_gather2(const float* __restrict__ b2,
                                                 float* __restrict__ out, int n) {
    const int t = threadIdx.x;
    const int g = (blockIdx.x * 256 + t) >> 2;
    const int m = t & 3;
    if (g >= n) return;

    const ull* G2 = (const ull*)s_g2;
    ull acc = G2[(size_t)g * 4 + m];            // self-loop term
    const int cnt  = s_cnt[g];
    const int pcnt = (cnt + 7) & ~7;
    const int* cp  = s_csr + s_row[g];

    for (int it = 0; it < pcnt; it += 8) {
        int ii[8];
        #pragma unroll
        for (int j = 0; j < 8; j++) ii[j] = __ldg(cp + it + j);
        ull v[8];
        #pragma unroll
        for (int j = 0; j < 8; j++) v[j] = __ldg(&G2[(size_t)ii[j] * 4 + m]);
        #pragma unroll
        for (int j = 0; j < 8; j++) ADD2(acc, acc, v[j]);
    }

    const float di = s_dinv[g];
    const int c0 = m * 2;
    float* orow = out + (size_t)g * NCLS;
    orow[c0] = fmaf(di, lo32(acc), __ldg(b2 + c0));
    if (c0 + 1 < NCLS)
        orow[c0 + 1] = fmaf(di, hi32(acc), __ldg(b2 + c0 + 1));
}

extern "C" void kernel_launch(void* const* d_in, const int* in_sizes, int n_in,
                              void* d_out, int out_size) {
    const float* x  = (const float*)d_in[0];
    const int*   ei = (const int*)  d_in[1];
    const float* W1 = (const float*)d_in[2];
    const float* b1 = (const float*)d_in[3];
    const float* W2 = (const float*)d_in[4];
    const float* b2 = (const float*)d_in[5];
    float* out = (float*)d_out;

    const int n = in_sizes[0] / IN_F;     // 100000
    const int e = in_sizes[1] / 2;        // 3200000
    const int* src = ei;
    const int* dst = ei + e;

    const int csr_len = e + 8 * n;        // padded CSR extent actually used
    const int csr4    = (csr_len + 3) / 4;

    const int nb = (n + 255) / 256;
    const int eb = (e + 255) / 256;
    const int zb = (csr4 > n ? csr4 + 255 : n + 255) / 256;
    const int gb = (n + G1_ROWS - 1) / G1_ROWS;
    const int g4 = (4 * n + 255) / 256;

    k_zero   <<<zb, 256>>>(n, csr4);
    k_hist   <<<eb, 256>>>(dst, e);
    k_scanA  <<<nb, 256>>>(n);
    k_scanC  <<<nb, 256>>>(n);
    k_fill   <<<eb, 256>>>(src, dst, e);
    k_gemm1  <<<gb, 256>>>(x, W1, n);
    k_gather1<<<g4, 256>>>(b1, W2, n);
    k_gather2<<<g4, 256>>>(b2, out, n);
}